// round 11
// baseline (speedup 1.0000x reference)
#include <cuda_runtime.h>
#include <cuda_fp16.h>
#include <cstdint>

#define NB 512
#define NN 128
#define ND 256
#define NTH 512
#define AP 132   // adj smem pitch

static __device__ __forceinline__ uint32_t h2(float lo, float hi){
    __half2 h = __floats2half2_rn(lo, hi);
    return *(uint32_t*)&h;
}

#define MMA16(C, A0,A1,A2,A3, B0, B1) \
    asm volatile("mma.sync.aligned.m16n8k16.row.col.f32.f16.f16.f32 " \
        "{%0,%1,%2,%3}, {%4,%5,%6,%7}, {%8,%9}, {%0,%1,%2,%3};" \
        : "+f"((C)[0]), "+f"((C)[1]), "+f"((C)[2]), "+f"((C)[3]) \
        : "r"(A0), "r"(A1), "r"(A2), "r"(A3), "r"(B0), "r"(B1))

__global__ __launch_bounds__(512, 1) void kmain(
    const float* __restrict__ x, const float* __restrict__ adj,
    const int* __restrict__ head, const float* __restrict__ lw,
    const float* __restrict__ bias, float* __restrict__ emb, float* __restrict__ nadj)
{
    extern __shared__ uint4 smq[];
    uint4* SAl = smq;            // 16 KB each
    uint4* SAh = smq + 1024;
    uint4* B1l = smq + 2048;     // adj(fp16) -> T1^T
    uint4* B1h = smq + 3072;
    uint4* B2l = smq + 4096;     // X0 -> X1
    uint4* B2h = smq + 5120;
    float* stage = (float*)(smq + 6144);   // adj fp32 cache -> nadj staging (128 x AP)

    __shared__ float sh_w[ND];
    __shared__ float sh_dinv[NN], sh_coef[NN], sh_dv[NN], sh_alpha[NN], sh_ca[NN], sh_sc[NN];
    __shared__ int   sh_flags[NN];
    __shared__ float sh_cut;

    const int b = blockIdx.x, tid = threadIdx.x;
    const int lane = tid & 31, wid = tid >> 5;
    const int g = lane >> 2, tg = lane & 3;
    const int ibw = wid >> 2, jbw = wid & 3;
    const int i0 = ibw * 32, j0 = jbw * 32;

    const float* xb = x + (size_t)b * NN * ND;
    const float* ab = adj + (size_t)b * NN * NN;
    float* adjf = stage;   // adj cached fp32, pitch AP (dead before nadj staging)

    // ---- coalesced one-time adj load into smem ----
    for (int u = tid; u < NN * NN; u += 512)
        adjf[(u >> 7) * AP + (u & 127)] = ab[u];
    if (tid < ND) sh_w[tid] = lw[tid];
    if (tid < NN) sh_flags[tid] = 0;
    if (tid == 0) sh_cut = 0.f;
    __syncthreads();

    sh_flags[head[(size_t)b * NTH + tid] & (NN - 1)] = 1;

    // ---- rowsum_r (LDS), v_r = x[r]·w (gmem, once) ----
    for (int r = wid; r < NN; r += 16){
        float s = 0.f, rs = 0.f;
        #pragma unroll
        for (int q = 0; q < 8; ++q) s += xb[r * ND + lane + q * 32] * sh_w[lane + q * 32];
        #pragma unroll
        for (int q = 0; q < 4; ++q) rs += adjf[r * AP + lane + q * 32];
        #pragma unroll
        for (int o = 16; o; o >>= 1){
            s  += __shfl_down_sync(~0u, s, o);
            rs += __shfl_down_sync(~0u, rs, o);
        }
        if (!lane){
            float di = rsqrtf(fmaxf(rs + 1.f, 1.f));
            sh_dinv[r] = di;
            sh_coef[r] = (rs > 0.f) ? di : 0.f;
            sh_dv[r]   = di * s;
        }
    }
    __syncthreads();

    // ---- alpha ----
    const float bia = bias[0];
    for (int r = wid; r < NN; r += 16){
        float t = 0.f;
        #pragma unroll
        for (int q = 0; q < 4; ++q){
            int m = lane + q * 32;
            t += adjf[r * AP + m] * sh_dv[m];
        }
        #pragma unroll
        for (int o = 16; o; o >>= 1) t += __shfl_down_sync(~0u, t, o);
        if (!lane){
            t += sh_dv[r];
            float o1 = sh_coef[r] * t + bia;
            sh_alpha[r] = 1.f / (1.f + __expf(-(o1 * o1)));
        }
    }
    const int nuniq = __syncthreads_count((tid < NN) ? sh_flags[tid] : 0);

    // ---- cut (k-th largest, tie-correct) ----
    if (nuniq > 1 && tid < NN){
        float a = sh_alpha[tid];
        int gt = 0, ge = 0;
        for (int j2 = 0; j2 < NN; ++j2){
            float aj = sh_alpha[j2];
            gt += (aj > a); ge += (aj >= a);
        }
        int k   = (nuniq + 9) / 10 + 1;
        int idx = min(k - 1, NN - 1);
        if (gt <= idx && idx < ge) sh_cut = a;
    }
    __syncthreads();
    if (tid < NN) sh_ca[tid] = fmaxf(sh_alpha[tid] + 1e-7f - sh_cut, 0.f);
    __syncthreads();

    // ---- sc_m = coef_m / max(coef_m * sum_j (adj+I)_mj dinv_j ca_j, eps) ----
    for (int m = wid; m < NN; m += 16){
        float ss = 0.f;
        #pragma unroll
        for (int q = 0; q < 4; ++q){
            int j = lane + q * 32;
            float a = adjf[m * AP + j] + ((j == m) ? 1.f : 0.f);
            ss += a * sh_dinv[j] * sh_ca[j];
        }
        #pragma unroll
        for (int o = 16; o; o >>= 1) ss += __shfl_down_sync(~0u, ss, o);
        if (!lane){
            float c = sh_coef[m];
            sh_sc[m] = c / fmaxf(c * ss, 1e-12f);
        }
    }
    __syncthreads();

    // ---- A-pack fill: S^T (fp16 fragment order), all adj reads from LDS ----
    for (int c = tid; c < 2048; c += 512){
        int ln = c & 31, ks = (c >> 5) & 7, ib = (c >> 8) & 3, sf = (c >> 10) & 1;
        int gp = ln >> 2, tp = ln & 3;
        int i = ib * 32 + sf * 16 + gp;
        int m0 = ks * 16 + 2 * tp;
        float fi  = sh_dinv[i] * sh_ca[i], fi8 = sh_dinv[i + 8] * sh_ca[i + 8];
        float s0 = sh_sc[m0], s1 = sh_sc[m0 + 1], s8 = sh_sc[m0 + 8], s9 = sh_sc[m0 + 9];
        uint32_t a0 = h2(s0 * (adjf[m0 * AP + i]       + (i == m0))       * fi,
                         s1 * (adjf[(m0 + 1) * AP + i] + (i == m0 + 1))   * fi);
        uint32_t a1 = h2(s0 * (adjf[m0 * AP + i + 8]       + (i + 8 == m0))     * fi8,
                         s1 * (adjf[(m0 + 1) * AP + i + 8] + (i + 8 == m0 + 1)) * fi8);
        uint32_t a2 = h2(s8 * (adjf[(m0 + 8) * AP + i] + (i == m0 + 8)) * fi,
                         s9 * (adjf[(m0 + 9) * AP + i] + (i == m0 + 9)) * fi);
        uint32_t a3 = h2(s8 * (adjf[(m0 + 8) * AP + i + 8] + (i + 8 == m0 + 8)) * fi8,
                         s9 * (adjf[(m0 + 9) * AP + i + 8] + (i + 8 == m0 + 9)) * fi8);
        (sf ? SAh : SAl)[(ib * 8 + ks) * 32 + ln] = make_uint4(a0, a1, a2, a3);
    }

    // ---- B-pack fills: adj(LDS) -> B1, X[:,0:128)(gmem once) -> B2 ----
    for (int c = tid; c < 2048; c += 512){
        int ln = c & 31, ks = (c >> 5) & 7, jb = (c >> 8) & 3, hf = (c >> 10) & 1;
        int gp = ln >> 2, tp = ln & 3;
        int m0 = ks * 16 + 2 * tp;
        int jA = jb * 32 + hf * 16 + gp, jB = jA + 8;
        (hf ? B1h : B1l)[(jb * 8 + ks) * 32 + ln] = make_uint4(
            h2(adjf[m0 * AP + jA], adjf[(m0 + 1) * AP + jA]),
            h2(adjf[(m0 + 8) * AP + jA], adjf[(m0 + 9) * AP + jA]),
            h2(adjf[m0 * AP + jB], adjf[(m0 + 1) * AP + jB]),
            h2(adjf[(m0 + 8) * AP + jB], adjf[(m0 + 9) * AP + jB]));
        (hf ? B2h : B2l)[(jb * 8 + ks) * 32 + ln] = make_uint4(
            h2(xb[m0 * ND + jA], xb[(m0 + 1) * ND + jA]),
            h2(xb[(m0 + 8) * ND + jA], xb[(m0 + 9) * ND + jA]),
            h2(xb[m0 * ND + jB], xb[(m0 + 1) * ND + jB]),
            h2(xb[(m0 + 8) * ND + jB], xb[(m0 + 9) * ND + jB]));
    }
    __syncthreads();

    const uint4* pAl = SAl + ibw * 256 + lane;
    const uint4* pAh = SAh + ibw * 256 + lane;
    const uint4* p1l = B1l + jbw * 256 + lane;
    const uint4* p1h = B1h + jbw * 256 + lane;
    const uint4* p2l = B2l + jbw * 256 + lane;
    const uint4* p2h = B2h + jbw * 256 + lane;

    float cT[2][4][4], cX[2][4][4];

    // ====== Phase A: T1 = S^T adj + emb0 = S^T X0 (shared A) ======
    #pragma unroll
    for (int s = 0; s < 2; ++s)
        #pragma unroll
        for (int jt = 0; jt < 4; ++jt)
            #pragma unroll
            for (int q = 0; q < 4; ++q){ cT[s][jt][q] = 0.f; cX[s][jt][q] = 0.f; }

    #pragma unroll
    for (int ks = 0; ks < 8; ++ks){
        uint4 a0 = pAl[ks * 32], a1 = pAh[ks * 32];
        uint4 u  = p1l[ks * 32], v  = p1h[ks * 32];
        uint4 p  = p2l[ks * 32], q4 = p2h[ks * 32];
        MMA16(cT[0][0], a0.x,a0.y,a0.z,a0.w, u.x, u.y);
        MMA16(cX[0][0], a0.x,a0.y,a0.z,a0.w, p.x, p.y);
        MMA16(cT[1][0], a1.x,a1.y,a1.z,a1.w, u.x, u.y);
        MMA16(cX[1][0], a1.x,a1.y,a1.z,a1.w, p.x, p.y);
        MMA16(cT[0][1], a0.x,a0.y,a0.z,a0.w, u.z, u.w);
        MMA16(cX[0][1], a0.x,a0.y,a0.z,a0.w, p.z, p.w);
        MMA16(cT[1][1], a1.x,a1.y,a1.z,a1.w, u.z, u.w);
        MMA16(cX[1][1], a1.x,a1.y,a1.z,a1.w, p.z, p.w);
        MMA16(cT[0][2], a0.x,a0.y,a0.z,a0.w, v.x, v.y);
        MMA16(cX[0][2], a0.x,a0.y,a0.z,a0.w, q4.x, q4.y);
        MMA16(cT[1][2], a1.x,a1.y,a1.z,a1.w, v.x, v.y);
        MMA16(cX[1][2], a1.x,a1.y,a1.z,a1.w, q4.x, q4.y);
        MMA16(cT[0][3], a0.x,a0.y,a0.z,a0.w, v.z, v.w);
        MMA16(cX[0][3], a0.x,a0.y,a0.z,a0.w, q4.z, q4.w);
        MMA16(cT[1][3], a1.x,a1.y,a1.z,a1.w, v.z, v.w);
        MMA16(cX[1][3], a1.x,a1.y,a1.z,a1.w, q4.z, q4.w);
    }
    __syncthreads();   // phase A reads of B1/B2 complete

    // ---- emb tile 0 ----
    {
        float* eb = emb + (size_t)b * NN * ND;
        #pragma unroll
        for (int s = 0; s < 2; ++s)
            #pragma unroll
            for (int jt = 0; jt < 4; ++jt){
                int r0 = i0 + s * 16 + g, col = j0 + jt * 8 + 2 * tg;
                *(float2*)(eb + r0 * ND + col)       = make_float2(cX[s][jt][0], cX[s][jt][1]);
                *(float2*)(eb + (r0 + 8) * ND + col) = make_float2(cX[s][jt][2], cX[s][jt][3]);
            }
    }

    // ---- scatter T1 as T1^T (B-pack) into B1 ----
    {
        uint32_t* B1u = (uint32_t*)B1l;   // B1h contiguous at +4096 u32
        #pragma unroll
        for (int s = 0; s < 2; ++s)
            #pragma unroll
            for (int jt = 0; jt < 4; ++jt){
                int c0 = j0 + jt * 8 + 2 * tg;
                int ksn = c0 >> 4, rem = c0 & 15;
                int mh = rem >> 3, tp = (rem & 7) >> 1;
                #pragma unroll
                for (int rs = 0; rs < 2; ++rs){
                    int rr = i0 + s * 16 + g + rs * 8;
                    uint32_t val = h2(cT[s][jt][rs * 2], cT[s][jt][rs * 2 + 1]);
                    int jb = rr >> 5, jtp = (rr >> 3) & 3, gg = rr & 7;
                    int lidx = (((jb * 8 + ksn) * 32 + gg * 4 + tp) << 2) + (jtp & 1) * 2 + mh;
                    B1u[(jtp >> 1) * 4096 + lidx] = val;
                }
            }
    }

    // ---- refill B2 with X[:,128:256) ----
    for (int c = tid; c < 2048; c += 512){
        int ln = c & 31, ks = (c >> 5) & 7, jb = (c >> 8) & 3, hf = (c >> 10) & 1;
        int gp = ln >> 2, tp = ln & 3;
        int m0 = ks * 16 + 2 * tp;
        int jA = jb * 32 + hf * 16 + gp + 128, jB = jA + 8;
        (hf ? B2h : B2l)[(jb * 8 + ks) * 32 + ln] = make_uint4(
            h2(xb[m0 * ND + jA], xb[(m0 + 1) * ND + jA]),
            h2(xb[(m0 + 8) * ND + jA], xb[(m0 + 9) * ND + jA]),
            h2(xb[m0 * ND + jB], xb[(m0 + 1) * ND + jB]),
            h2(xb[(m0 + 8) * ND + jB], xb[(m0 + 9) * ND + jB]));
    }
    __syncthreads();

    // ====== Phase B: nadj^T = S^T T1^T + emb1 = S^T X1 (shared A) ======
    #pragma unroll
    for (int s = 0; s < 2; ++s)
        #pragma unroll
        for (int jt = 0; jt < 4; ++jt)
            #pragma unroll
            for (int q = 0; q < 4; ++q){ cT[s][jt][q] = 0.f; cX[s][jt][q] = 0.f; }

    #pragma unroll
    for (int ks = 0; ks < 8; ++ks){
        uint4 a0 = pAl[ks * 32], a1 = pAh[ks * 32];
        uint4 u  = p1l[ks * 32], v  = p1h[ks * 32];
        uint4 p  = p2l[ks * 32], q4 = p2h[ks * 32];
        MMA16(cT[0][0], a0.x,a0.y,a0.z,a0.w, u.x, u.y);
        MMA16(cX[0][0], a0.x,a0.y,a0.z,a0.w, p.x, p.y);
        MMA16(cT[1][0], a1.x,a1.y,a1.z,a1.w, u.x, u.y);
        MMA16(cX[1][0], a1.x,a1.y,a1.z,a1.w, p.x, p.y);
        MMA16(cT[0][1], a0.x,a0.y,a0.z,a0.w, u.z, u.w);
        MMA16(cX[0][1], a0.x,a0.y,a0.z,a0.w, p.z, p.w);
        MMA16(cT[1][1], a1.x,a1.y,a1.z,a1.w, u.z, u.w);
        MMA16(cX[1][1], a1.x,a1.y,a1.z,a1.w, p.z, p.w);
        MMA16(cT[0][2], a0.x,a0.y,a0.z,a0.w, v.x, v.y);
        MMA16(cX[0][2], a0.x,a0.y,a0.z,a0.w, q4.x, q4.y);
        MMA16(cT[1][2], a1.x,a1.y,a1.z,a1.w, v.x, v.y);
        MMA16(cX[1][2], a1.x,a1.y,a1.z,a1.w, q4.x, q4.y);
        MMA16(cT[0][3], a0.x,a0.y,a0.z,a0.w, v.z, v.w);
        MMA16(cX[0][3], a0.x,a0.y,a0.z,a0.w, q4.z, q4.w);
        MMA16(cT[1][3], a1.x,a1.y,a1.z,a1.w, v.z, v.w);
        MMA16(cX[1][3], a1.x,a1.y,a1.z,a1.w, q4.z, q4.w);
    }

    // ---- emb tile 1 (direct) ----
    {
        float* eb = emb + (size_t)b * NN * ND + 128;
        #pragma unroll
        for (int s = 0; s < 2; ++s)
            #pragma unroll
            for (int jt = 0; jt < 4; ++jt){
                int r0 = i0 + s * 16 + g, col = j0 + jt * 8 + 2 * tg;
                *(float2*)(eb + r0 * ND + col)       = make_float2(cX[s][jt][0], cX[s][jt][1]);
                *(float2*)(eb + (r0 + 8) * ND + col) = make_float2(cX[s][jt][2], cX[s][jt][3]);
            }
    }

    // ---- nadj: stage transpose in smem (adjf is dead now), coalesced store ----
    __syncthreads();   // everyone done reading adjf
    #pragma unroll
    for (int s = 0; s < 2; ++s)
        #pragma unroll
        for (int jt = 0; jt < 4; ++jt)
            #pragma unroll
            for (int q = 0; q < 4; ++q){
                int col = j0 + jt * 8 + 2 * tg + (q & 1);
                int row = i0 + s * 16 + g + ((q >> 1) * 8);
                stage[col * AP + row] = cT[s][jt][q];   // stage[a][b] = nadj[a][b]
            }
    __syncthreads();
    {
        float* nb = nadj + (size_t)b * NN * NN;
        for (int idx = tid; idx < 4096; idx += 512){
            int a = idx >> 5, bq = (idx & 31) * 4;
            *(float4*)(nb + a * NN + bq) = *(const float4*)(stage + a * AP + bq);
        }
    }
}

extern "C" void kernel_launch(void* const* d_in, const int* in_sizes, int n_in,
                              void* d_out, int out_size) {
    const float* x    = (const float*)d_in[0];
    const float* adj  = (const float*)d_in[1];
    const int*   head = (const int*)d_in[2];
    const float* lw   = (const float*)d_in[3];
    const float* bias = (const float*)d_in[4];

    float* out  = (float*)d_out;
    float* emb  = out;                            // [B, N, D]
    float* nadj = out + (size_t)NB * NN * ND;     // [B, N, N]

    const int dsmem = 6144 * 16 + NN * AP * 4;    // 98304 + 67584 = 165,888 B
    cudaFuncSetAttribute(kmain, cudaFuncAttributeMaxDynamicSharedMemorySize, dsmem);
    kmain<<<NB, 512, dsmem>>>(x, adj, head, lw, bias, emb, nadj);
}

// round 12
// speedup vs baseline: 1.0649x; 1.0649x over previous
#include <cuda_runtime.h>
#include <cuda_fp16.h>
#include <cstdint>

#define NB 512
#define NN 128
#define ND 256
#define NTH 512

static __device__ __forceinline__ uint32_t h2(float lo, float hi){
    __half2 h = __floats2half2_rn(lo, hi);
    return *(uint32_t*)&h;
}

#define MMA16(C, A, B0, B1) \
    asm volatile("mma.sync.aligned.m16n8k16.row.col.f32.f16.f16.f32 " \
        "{%0,%1,%2,%3}, {%4,%5,%6,%7}, {%8,%9}, {%0,%1,%2,%3};" \
        : "+f"((C)[0]), "+f"((C)[1]), "+f"((C)[2]), "+f"((C)[3]) \
        : "r"((A).x), "r"((A).y), "r"((A).z), "r"((A).w), "r"(B0), "r"(B1))

// 32x64 warp tile, K=128 (8 k-steps), A shared across row-halves s=0/1.
static __device__ __forceinline__ void kloop(
    float (&acc)[2][8][4],
    const uint4* __restrict__ pAl, const uint4* __restrict__ pAh,
    const uint4* __restrict__ b0l, const uint4* __restrict__ b0h,
    const uint4* __restrict__ b1l, const uint4* __restrict__ b1h)
{
    #pragma unroll
    for (int ks = 0; ks < 8; ++ks){
        uint4 a0 = pAl[ks * 32], a1 = pAh[ks * 32];
        uint4 u0 = b0l[ks * 32], v0 = b0h[ks * 32];
        uint4 u1 = b1l[ks * 32], v1 = b1h[ks * 32];
        MMA16(acc[0][0], a0, u0.x, u0.y);  MMA16(acc[1][0], a1, u0.x, u0.y);
        MMA16(acc[0][1], a0, u0.z, u0.w);  MMA16(acc[1][1], a1, u0.z, u0.w);
        MMA16(acc[0][2], a0, v0.x, v0.y);  MMA16(acc[1][2], a1, v0.x, v0.y);
        MMA16(acc[0][3], a0, v0.z, v0.w);  MMA16(acc[1][3], a1, v0.z, v0.w);
        MMA16(acc[0][4], a0, u1.x, u1.y);  MMA16(acc[1][4], a1, u1.x, u1.y);
        MMA16(acc[0][5], a0, u1.z, u1.w);  MMA16(acc[1][5], a1, u1.z, u1.w);
        MMA16(acc[0][6], a0, v1.x, v1.y);  MMA16(acc[1][6], a1, v1.x, v1.y);
        MMA16(acc[0][7], a0, v1.z, v1.w);  MMA16(acc[1][7], a1, v1.z, v1.w);
    }
}

static __device__ __forceinline__ void zacc(float (&acc)[2][8][4]){
    #pragma unroll
    for (int s = 0; s < 2; ++s)
        #pragma unroll
        for (int jt = 0; jt < 8; ++jt)
            #pragma unroll
            for (int q = 0; q < 4; ++q) acc[s][jt][q] = 0.f;
}

__global__ __launch_bounds__(256, 2) void kmain(
    const float* __restrict__ x, const float* __restrict__ adj,
    const int* __restrict__ head, const float* __restrict__ lw,
    const float* __restrict__ bias, float* __restrict__ emb, float* __restrict__ nadj)
{
    extern __shared__ uint4 smq[];
    uint4* SAl = smq;            // 16 KB each; total 96 KB
    uint4* SAh = smq + 1024;
    uint4* B1l = smq + 2048;     // adj(fp16) -> T1^T
    uint4* B1h = smq + 3072;
    uint4* B2l = smq + 4096;     // X0 -> X1
    uint4* B2h = smq + 5120;

    __shared__ float sh_w[ND];
    __shared__ float sh_dinv[NN], sh_coef[NN], sh_dv[NN], sh_alpha[NN], sh_ca[NN], sh_sc[NN];
    __shared__ int   sh_flags[NN];
    __shared__ float sh_cut;

    const int b = blockIdx.x, tid = threadIdx.x;
    const int lane = tid & 31, wid = tid >> 5;     // 8 warps
    const int g = lane >> 2, tg = lane & 3;
    const int iw = wid >> 1, jw = wid & 1;
    const int i0 = iw * 32, j0 = jw * 64;

    const float* xb = x + (size_t)b * NN * ND;
    const float* ab = adj + (size_t)b * NN * NN;

    sh_w[tid] = lw[tid];
    if (tid < NN) sh_flags[tid] = 0;
    if (tid == 0) sh_cut = 0.f;
    __syncthreads();

    sh_flags[head[(size_t)b * NTH + tid]       & (NN - 1)] = 1;
    sh_flags[head[(size_t)b * NTH + tid + 256] & (NN - 1)] = 1;

    // ---- rowsum_r, v_r = x[r]·w ----
    for (int r = wid; r < NN; r += 8){
        float s = 0.f, rs = 0.f;
        #pragma unroll
        for (int q = 0; q < 8; ++q) s += xb[r * ND + lane + q * 32] * sh_w[lane + q * 32];
        #pragma unroll
        for (int q = 0; q < 4; ++q) rs += ab[r * NN + lane + q * 32];
        #pragma unroll
        for (int o = 16; o; o >>= 1){
            s  += __shfl_down_sync(~0u, s, o);
            rs += __shfl_down_sync(~0u, rs, o);
        }
        if (!lane){
            float di = rsqrtf(fmaxf(rs + 1.f, 1.f));
            sh_dinv[r] = di;
            sh_coef[r] = (rs > 0.f) ? di : 0.f;
            sh_dv[r]   = di * s;
        }
    }
    __syncthreads();

    // ---- alpha ----
    const float bia = bias[0];
    for (int r = wid; r < NN; r += 8){
        float t = 0.f;
        #pragma unroll
        for (int q = 0; q < 4; ++q){
            int m = lane + q * 32;
            t += ab[r * NN + m] * sh_dv[m];
        }
        #pragma unroll
        for (int o = 16; o; o >>= 1) t += __shfl_down_sync(~0u, t, o);
        if (!lane){
            t += sh_dv[r];
            float o1 = sh_coef[r] * t + bia;
            sh_alpha[r] = 1.f / (1.f + __expf(-(o1 * o1)));
        }
    }
    const int nuniq = __syncthreads_count((tid < NN) ? sh_flags[tid] : 0);

    // ---- cut (k-th largest, tie-correct) ----
    if (nuniq > 1 && tid < NN){
        float a = sh_alpha[tid];
        int gt = 0, ge = 0;
        for (int j2 = 0; j2 < NN; ++j2){
            float aj = sh_alpha[j2];
            gt += (aj > a); ge += (aj >= a);
        }
        int k   = (nuniq + 9) / 10 + 1;
        int idx = min(k - 1, NN - 1);
        if (gt <= idx && idx < ge) sh_cut = a;
    }
    __syncthreads();
    if (tid < NN) sh_ca[tid] = fmaxf(sh_alpha[tid] + 1e-7f - sh_cut, 0.f);
    __syncthreads();

    // ---- sc_m ----
    for (int m = wid; m < NN; m += 8){
        float ss = 0.f;
        #pragma unroll
        for (int q = 0; q < 4; ++q){
            int j = lane + q * 32;
            float a = ab[m * NN + j] + ((j == m) ? 1.f : 0.f);
            ss += a * sh_dinv[j] * sh_ca[j];
        }
        #pragma unroll
        for (int o = 16; o; o >>= 1) ss += __shfl_down_sync(~0u, ss, o);
        if (!lane){
            float c = sh_coef[m];
            sh_sc[m] = c / fmaxf(c * ss, 1e-12f);
        }
    }
    __syncthreads();

    // ---- A-pack fill: S^T (fp16 fragment order) ----
    for (int c = tid; c < 2048; c += 256){
        int ln = c & 31, ks = (c >> 5) & 7, ib = (c >> 8) & 3, sf = (c >> 10) & 1;
        int gp = ln >> 2, tp = ln & 3;
        int i = ib * 32 + sf * 16 + gp;
        int m0 = ks * 16 + 2 * tp;
        float fi  = sh_dinv[i] * sh_ca[i], fi8 = sh_dinv[i + 8] * sh_ca[i + 8];
        float s0 = sh_sc[m0], s1 = sh_sc[m0 + 1], s8 = sh_sc[m0 + 8], s9 = sh_sc[m0 + 9];
        uint32_t a0 = h2(s0 * (ab[m0 * NN + i]       + (i == m0))       * fi,
                         s1 * (ab[(m0 + 1) * NN + i] + (i == m0 + 1))   * fi);
        uint32_t a1 = h2(s0 * (ab[m0 * NN + i + 8]       + (i + 8 == m0))     * fi8,
                         s1 * (ab[(m0 + 1) * NN + i + 8] + (i + 8 == m0 + 1)) * fi8);
        uint32_t a2 = h2(s8 * (ab[(m0 + 8) * NN + i] + (i == m0 + 8)) * fi,
                         s9 * (ab[(m0 + 9) * NN + i] + (i == m0 + 9)) * fi);
        uint32_t a3 = h2(s8 * (ab[(m0 + 8) * NN + i + 8] + (i + 8 == m0 + 8)) * fi8,
                         s9 * (ab[(m0 + 9) * NN + i + 8] + (i + 8 == m0 + 9)) * fi8);
        (sf ? SAh : SAl)[(ib * 8 + ks) * 32 + ln] = make_uint4(a0, a1, a2, a3);
    }

    // ---- B-pack fills: adj -> B1, X[:,0:128) -> B2 ----
    for (int c = tid; c < 2048; c += 256){
        int ln = c & 31, ks = (c >> 5) & 7, jb = (c >> 8) & 3, hf = (c >> 10) & 1;
        int gp = ln >> 2, tp = ln & 3;
        int m0 = ks * 16 + 2 * tp;
        int jA = jb * 32 + hf * 16 + gp, jB = jA + 8;
        (hf ? B1h : B1l)[(jb * 8 + ks) * 32 + ln] = make_uint4(
            h2(ab[m0 * NN + jA], ab[(m0 + 1) * NN + jA]),
            h2(ab[(m0 + 8) * NN + jA], ab[(m0 + 9) * NN + jA]),
            h2(ab[m0 * NN + jB], ab[(m0 + 1) * NN + jB]),
            h2(ab[(m0 + 8) * NN + jB], ab[(m0 + 9) * NN + jB]));
        (hf ? B2h : B2l)[(jb * 8 + ks) * 32 + ln] = make_uint4(
            h2(xb[m0 * ND + jA], xb[(m0 + 1) * ND + jA]),
            h2(xb[(m0 + 8) * ND + jA], xb[(m0 + 9) * ND + jA]),
            h2(xb[m0 * ND + jB], xb[(m0 + 1) * ND + jB]),
            h2(xb[(m0 + 8) * ND + jB], xb[(m0 + 9) * ND + jB]));
    }
    __syncthreads();

    const uint4* pAl = SAl + iw * 256 + lane;
    const uint4* pAh = SAh + iw * 256 + lane;
    const int jb0 = jw * 2;
    const uint4* q1l0 = B1l + jb0 * 256 + lane;
    const uint4* q1h0 = B1h + jb0 * 256 + lane;
    const uint4* q1l1 = B1l + (jb0 + 1) * 256 + lane;
    const uint4* q1h1 = B1h + (jb0 + 1) * 256 + lane;
    const uint4* q2l0 = B2l + jb0 * 256 + lane;
    const uint4* q2h0 = B2h + jb0 * 256 + lane;
    const uint4* q2l1 = B2l + (jb0 + 1) * 256 + lane;
    const uint4* q2h1 = B2h + (jb0 + 1) * 256 + lane;

    float acc[2][8][4];

    // ====== G1: T1 = S^T adj ======
    zacc(acc);
    kloop(acc, pAl, pAh, q1l0, q1h0, q1l1, q1h1);
    __syncthreads();   // all reads of B1 done

    // ---- scatter T1 as T1^T (B-pack) into B1 ----
    {
        uint32_t* B1u = (uint32_t*)B1l;   // B1h contiguous at +4096 u32
        #pragma unroll
        for (int s = 0; s < 2; ++s)
            #pragma unroll
            for (int jt = 0; jt < 8; ++jt){
                int c0 = j0 + jt * 8 + 2 * tg;
                int ksn = c0 >> 4, rem = c0 & 15;
                int mh = rem >> 3, tp = (rem & 7) >> 1;
                #pragma unroll
                for (int rs = 0; rs < 2; ++rs){
                    int rr = i0 + s * 16 + g + rs * 8;
                    uint32_t val = h2(acc[s][jt][rs * 2], acc[s][jt][rs * 2 + 1]);
                    int jb = rr >> 5, jtp = (rr >> 3) & 3, gg = rr & 7;
                    int lidx = (((jb * 8 + ksn) * 32 + gg * 4 + tp) << 2) + (jtp & 1) * 2 + mh;
                    B1u[(jtp >> 1) * 4096 + lidx] = val;
                }
            }
    }

    // ====== G2a: emb0 = S^T X0 ======
    zacc(acc);
    kloop(acc, pAl, pAh, q2l0, q2h0, q2l1, q2h1);
    {
        float* eb = emb + (size_t)b * NN * ND;
        #pragma unroll
        for (int s = 0; s < 2; ++s)
            #pragma unroll
            for (int jt = 0; jt < 8; ++jt){
                int r0 = i0 + s * 16 + g, col = j0 + jt * 8 + 2 * tg;
                *(float2*)(eb + r0 * ND + col)       = make_float2(acc[s][jt][0], acc[s][jt][1]);
                *(float2*)(eb + (r0 + 8) * ND + col) = make_float2(acc[s][jt][2], acc[s][jt][3]);
            }
    }
    __syncthreads();   // T1^T scatter visible; B2 reads done

    // ---- refill B2 with X[:,128:256) ----
    for (int c = tid; c < 2048; c += 256){
        int ln = c & 31, ks = (c >> 5) & 7, jb = (c >> 8) & 3, hf = (c >> 10) & 1;
        int gp = ln >> 2, tp = ln & 3;
        int m0 = ks * 16 + 2 * tp;
        int jA = jb * 32 + hf * 16 + gp + 128, jB = jA + 8;
        (hf ? B2h : B2l)[(jb * 8 + ks) * 32 + ln] = make_uint4(
            h2(xb[m0 * ND + jA], xb[(m0 + 1) * ND + jA]),
            h2(xb[(m0 + 8) * ND + jA], xb[(m0 + 9) * ND + jA]),
            h2(xb[m0 * ND + jB], xb[(m0 + 1) * ND + jB]),
            h2(xb[(m0 + 8) * ND + jB], xb[(m0 + 9) * ND + jB]));
    }

    // ====== G3: nadj^T = S^T T1^T ======
    zacc(acc);
    kloop(acc, pAl, pAh, q1l0, q1h0, q1l1, q1h1);
    {
        // acc = nadj^T tile: value at (row=i0+s*16+g+8*(q>>1), col=j0+jt*8+2tg+(q&1))
        // nadj[col][row] = value. Per (s,jt,q): 8 lanes (g) hit consecutive rows -> 32B segments.
        float* nb = nadj + (size_t)b * NN * NN;
        #pragma unroll
        for (int s = 0; s < 2; ++s)
            #pragma unroll
            for (int jt = 0; jt < 8; ++jt){
                int col = j0 + jt * 8 + 2 * tg;
                int row = i0 + s * 16 + g;
                nb[col * NN + row]           = acc[s][jt][0];
                nb[(col + 1) * NN + row]     = acc[s][jt][1];
                nb[col * NN + row + 8]       = acc[s][jt][2];
                nb[(col + 1) * NN + row + 8] = acc[s][jt][3];
            }
    }
    __syncthreads();   // B2 refill visible to all

    // ====== G2b: emb1 = S^T X1 ======
    zacc(acc);
    kloop(acc, pAl, pAh, q2l0, q2h0, q2l1, q2h1);
    {
        float* eb = emb + (size_t)b * NN * ND + 128;
        #pragma unroll
        for (int s = 0; s < 2; ++s)
            #pragma unroll
            for (int jt = 0; jt < 8; ++jt){
                int r0 = i0 + s * 16 + g, col = j0 + jt * 8 + 2 * tg;
                *(float2*)(eb + r0 * ND + col)       = make_float2(acc[s][jt][0], acc[s][jt][1]);
                *(float2*)(eb + (r0 + 8) * ND + col) = make_float2(acc[s][jt][2], acc[s][jt][3]);
            }
    }
}

extern "C" void kernel_launch(void* const* d_in, const int* in_sizes, int n_in,
                              void* d_out, int out_size) {
    const float* x    = (const float*)d_in[0];
    const float* adj  = (const float*)d_in[1];
    const int*   head = (const int*)d_in[2];
    const float* lw   = (const float*)d_in[3];
    const float* bias = (const float*)d_in[4];

    float* out  = (float*)d_out;
    float* emb  = out;                            // [B, N, D]
    float* nadj = out + (size_t)NB * NN * ND;     // [B, N, N]

    const int dsmem = 6144 * 16;                  // 98,304 B — fits 2 CTAs/SM
    cudaFuncSetAttribute(kmain, cudaFuncAttributeMaxDynamicSharedMemorySize, dsmem);
    kmain<<<NB, 256, dsmem>>>(x, adj, head, lw, bias, emb, nadj);
}

// round 13
// speedup vs baseline: 1.0746x; 1.0091x over previous
#include <cuda_runtime.h>
#include <cuda_fp16.h>
#include <cstdint>

#define NB 512
#define NN 128
#define ND 256
#define NTH 512

static __device__ __forceinline__ uint32_t h2(float lo, float hi){
    __half2 h = __floats2half2_rn(lo, hi);
    return *(uint32_t*)&h;
}

#define MMA16(C, A, B0, B1) \
    asm volatile("mma.sync.aligned.m16n8k16.row.col.f32.f16.f16.f32 " \
        "{%0,%1,%2,%3}, {%4,%5,%6,%7}, {%8,%9}, {%0,%1,%2,%3};" \
        : "+f"((C)[0]), "+f"((C)[1]), "+f"((C)[2]), "+f"((C)[3]) \
        : "r"((A).x), "r"((A).y), "r"((A).z), "r"((A).w), "r"(B0), "r"(B1))

static __device__ __forceinline__ void kloop(
    float (&acc)[2][8][4],
    const uint4* __restrict__ pAl, const uint4* __restrict__ pAh,
    const uint4* __restrict__ b0l, const uint4* __restrict__ b0h,
    const uint4* __restrict__ b1l, const uint4* __restrict__ b1h)
{
    #pragma unroll
    for (int ks = 0; ks < 8; ++ks){
        uint4 a0 = pAl[ks * 32], a1 = pAh[ks * 32];
        uint4 u0 = b0l[ks * 32], v0 = b0h[ks * 32];
        uint4 u1 = b1l[ks * 32], v1 = b1h[ks * 32];
        MMA16(acc[0][0], a0, u0.x, u0.y);  MMA16(acc[1][0], a1, u0.x, u0.y);
        MMA16(acc[0][1], a0, u0.z, u0.w);  MMA16(acc[1][1], a1, u0.z, u0.w);
        MMA16(acc[0][2], a0, v0.x, v0.y);  MMA16(acc[1][2], a1, v0.x, v0.y);
        MMA16(acc[0][3], a0, v0.z, v0.w);  MMA16(acc[1][3], a1, v0.z, v0.w);
        MMA16(acc[0][4], a0, u1.x, u1.y);  MMA16(acc[1][4], a1, u1.x, u1.y);
        MMA16(acc[0][5], a0, u1.z, u1.w);  MMA16(acc[1][5], a1, u1.z, u1.w);
        MMA16(acc[0][6], a0, v1.x, v1.y);  MMA16(acc[1][6], a1, v1.x, v1.y);
        MMA16(acc[0][7], a0, v1.z, v1.w);  MMA16(acc[1][7], a1, v1.z, v1.w);
    }
}

static __device__ __forceinline__ void zacc(float (&acc)[2][8][4]){
    #pragma unroll
    for (int s = 0; s < 2; ++s)
        #pragma unroll
        for (int jt = 0; jt < 8; ++jt)
            #pragma unroll
            for (int q = 0; q < 4; ++q) acc[s][jt][q] = 0.f;
}

__global__ __launch_bounds__(256, 2) void kmain(
    const float* __restrict__ x, const float* __restrict__ adj,
    const int* __restrict__ head, const float* __restrict__ lw,
    const float* __restrict__ bias, float* __restrict__ emb, float* __restrict__ nadj)
{
    extern __shared__ uint4 smq[];
    uint4* SAl = smq;            // 16 KB each; total 96 KB
    uint4* SAh = smq + 1024;
    uint4* B1l = smq + 2048;     // adj(fp16) -> T1^T
    uint4* B1h = smq + 3072;
    uint4* B2l = smq + 4096;     // X0 -> X1
    uint4* B2h = smq + 5120;

    __shared__ __align__(16) float sh_w[ND];
    __shared__ __align__(16) float sh_dinv[NN], sh_coef[NN], sh_dv[NN];
    __shared__ __align__(16) float sh_alpha[NN], sh_ca[NN], sh_sc[NN], sh_pc[NN];
    __shared__ int   sh_flags[NN];
    __shared__ float sh_cut;

    const int b = blockIdx.x, tid = threadIdx.x;
    const int lane = tid & 31, wid = tid >> 5;     // 8 warps
    const int g = lane >> 2, tg = lane & 3;
    const int iw = wid >> 1, jw = wid & 1;
    const int i0 = iw * 32, j0 = jw * 64;

    const float* xb = x + (size_t)b * NN * ND;
    const float* ab = adj + (size_t)b * NN * NN;

    sh_w[tid] = lw[tid];
    if (tid < NN) sh_flags[tid] = 0;
    if (tid == 0) sh_cut = 0.f;
    __syncthreads();

    sh_flags[head[(size_t)b * NTH + tid]       & (NN - 1)] = 1;
    sh_flags[head[(size_t)b * NTH + tid + 256] & (NN - 1)] = 1;

    // row-parallel prologue: thread pair (2r, 2r+1) owns row r; halves h=0/1.
    const int r2 = tid >> 1, hf2 = tid & 1;
    const float4* arow = (const float4*)(ab + r2 * NN + hf2 * 64);   // 16 float4

    // ---- L1: rowsum(adj row) + v = x[r]·w ----
    {
        float rs = 0.f, s = 0.f;
        #pragma unroll
        for (int q = 0; q < 16; ++q){
            float4 v = arow[q];
            rs += (v.x + v.y) + (v.z + v.w);
        }
        const float4* xrow = (const float4*)(xb + r2 * ND + hf2 * 128);  // 32 float4
        const float4* wv4  = (const float4*)(sh_w) + hf2 * 32;
        #pragma unroll
        for (int q = 0; q < 32; ++q){
            float4 v = xrow[q], w4 = wv4[q];
            s += v.x * w4.x + v.y * w4.y + v.z * w4.z + v.w * w4.w;
        }
        rs += __shfl_xor_sync(~0u, rs, 1);
        s  += __shfl_xor_sync(~0u, s, 1);
        if (!hf2){
            float di = rsqrtf(fmaxf(rs + 1.f, 1.f));
            sh_dinv[r2] = di;
            sh_coef[r2] = (rs > 0.f) ? di : 0.f;
            sh_dv[r2]   = di * s;
        }
    }
    __syncthreads();

    // ---- L2: alpha_r = sigmoid((coef_r*(adj[r]·dv + dv_r) + bias)^2) ----
    const float bia = bias[0];
    {
        float t = 0.f;
        const float4* dv4 = (const float4*)(sh_dv) + hf2 * 16;
        #pragma unroll
        for (int q = 0; q < 16; ++q){
            float4 v = arow[q], d4 = dv4[q];
            t += v.x * d4.x + v.y * d4.y + v.z * d4.z + v.w * d4.w;
        }
        t += __shfl_xor_sync(~0u, t, 1);
        if (!hf2){
            t += sh_dv[r2];
            float o1 = sh_coef[r2] * t + bia;
            sh_alpha[r2] = 1.f / (1.f + __expf(-(o1 * o1)));
        }
    }
    const int nuniq = __syncthreads_count((tid < NN) ? sh_flags[tid] : 0);

    // ---- cut (k-th largest, tie-correct) ----
    if (nuniq > 1 && tid < NN){
        float a = sh_alpha[tid];
        int gt = 0, ge = 0;
        const float4* al4 = (const float4*)sh_alpha;
        #pragma unroll
        for (int q = 0; q < 32; ++q){
            float4 v = al4[q];
            gt += (v.x > a) + (v.y > a) + (v.z > a) + (v.w > a);
            ge += (v.x >= a) + (v.y >= a) + (v.z >= a) + (v.w >= a);
        }
        int k   = (nuniq + 9) / 10 + 1;
        int idx = min(k - 1, NN - 1);
        if (gt <= idx && idx < ge) sh_cut = a;
    }
    __syncthreads();
    if (tid < NN){
        float ca = fmaxf(sh_alpha[tid] + 1e-7f - sh_cut, 0.f);
        sh_ca[tid] = ca;
        sh_pc[tid] = sh_dinv[tid] * ca;   // pc_j = dinv_j * ca_j
    }
    __syncthreads();

    // ---- L3: sc_m = coef_m / max(coef_m * (adj[m]·pc + pc_m), eps) ----
    {
        float ss = 0.f;
        const float4* pc4 = (const float4*)(sh_pc) + hf2 * 16;
        #pragma unroll
        for (int q = 0; q < 16; ++q){
            float4 v = arow[q], p4 = pc4[q];
            ss += v.x * p4.x + v.y * p4.y + v.z * p4.z + v.w * p4.w;
        }
        ss += __shfl_xor_sync(~0u, ss, 1);
        if (!hf2){
            ss += sh_pc[r2];               // identity term (adj+I)
            float c = sh_coef[r2];
            sh_sc[r2] = c / fmaxf(c * ss, 1e-12f);
        }
    }
    __syncthreads();

    // ---- A-pack fill: S^T (fp16 fragment order); S[m][i] = sc_m*(adj_mi+I)*pc_i ----
    for (int c = tid; c < 2048; c += 256){
        int ln = c & 31, ks = (c >> 5) & 7, ib = (c >> 8) & 3, sf = (c >> 10) & 1;
        int gp = ln >> 2, tp = ln & 3;
        int i = ib * 32 + sf * 16 + gp;
        int m0 = ks * 16 + 2 * tp;
        float fi = sh_pc[i], fi8 = sh_pc[i + 8];
        float s0 = sh_sc[m0], s1 = sh_sc[m0 + 1], s8 = sh_sc[m0 + 8], s9 = sh_sc[m0 + 9];
        uint32_t a0 = h2(s0 * (ab[m0 * NN + i]       + (i == m0))       * fi,
                         s1 * (ab[(m0 + 1) * NN + i] + (i == m0 + 1))   * fi);
        uint32_t a1 = h2(s0 * (ab[m0 * NN + i + 8]       + (i + 8 == m0))     * fi8,
                         s1 * (ab[(m0 + 1) * NN + i + 8] + (i + 8 == m0 + 1)) * fi8);
        uint32_t a2 = h2(s8 * (ab[(m0 + 8) * NN + i] + (i == m0 + 8)) * fi,
                         s9 * (ab[(m0 + 9) * NN + i] + (i == m0 + 9)) * fi);
        uint32_t a3 = h2(s8 * (ab[(m0 + 8) * NN + i + 8] + (i + 8 == m0 + 8)) * fi8,
                         s9 * (ab[(m0 + 9) * NN + i + 8] + (i + 8 == m0 + 9)) * fi8);
        (sf ? SAh : SAl)[(ib * 8 + ks) * 32 + ln] = make_uint4(a0, a1, a2, a3);
    }

    // ---- B-pack fills: adj -> B1, X[:,0:128) -> B2 ----
    for (int c = tid; c < 2048; c += 256){
        int ln = c & 31, ks = (c >> 5) & 7, jb = (c >> 8) & 3, hf = (c >> 10) & 1;
        int gp = ln >> 2, tp = ln & 3;
        int m0 = ks * 16 + 2 * tp;
        int jA = jb * 32 + hf * 16 + gp, jB = jA + 8;
        (hf ? B1h : B1l)[(jb * 8 + ks) * 32 + ln] = make_uint4(
            h2(ab[m0 * NN + jA], ab[(m0 + 1) * NN + jA]),
            h2(ab[(m0 + 8) * NN + jA], ab[(m0 + 9) * NN + jA]),
            h2(ab[m0 * NN + jB], ab[(m0 + 1) * NN + jB]),
            h2(ab[(m0 + 8) * NN + jB], ab[(m0 + 9) * NN + jB]));
        (hf ? B2h : B2l)[(jb * 8 + ks) * 32 + ln] = make_uint4(
            h2(xb[m0 * ND + jA], xb[(m0 + 1) * ND + jA]),
            h2(xb[(m0 + 8) * ND + jA], xb[(m0 + 9) * ND + jA]),
            h2(xb[m0 * ND + jB], xb[(m0 + 1) * ND + jB]),
            h2(xb[(m0 + 8) * ND + jB], xb[(m0 + 9) * ND + jB]));
    }
    __syncthreads();

    const uint4* pAl = SAl + iw * 256 + lane;
    const uint4* pAh = SAh + iw * 256 + lane;
    const int jb0 = jw * 2;
    const uint4* q1l0 = B1l + jb0 * 256 + lane;
    const uint4* q1h0 = B1h + jb0 * 256 + lane;
    const uint4* q1l1 = B1l + (jb0 + 1) * 256 + lane;
    const uint4* q1h1 = B1h + (jb0 + 1) * 256 + lane;
    const uint4* q2l0 = B2l + jb0 * 256 + lane;
    const uint4* q2h0 = B2h + jb0 * 256 + lane;
    const uint4* q2l1 = B2l + (jb0 + 1) * 256 + lane;
    const uint4* q2h1 = B2h + (jb0 + 1) * 256 + lane;

    float acc[2][8][4];

    // ====== G1: T1 = S^T adj ======
    zacc(acc);
    kloop(acc, pAl, pAh, q1l0, q1h0, q1l1, q1h1);
    __syncthreads();   // all reads of B1 done

    // ---- scatter T1 as T1^T (B-pack) into B1 ----
    {
        uint32_t* B1u = (uint32_t*)B1l;   // B1h contiguous at +4096 u32
        #pragma unroll
        for (int s = 0; s < 2; ++s)
            #pragma unroll
            for (int jt = 0; jt < 8; ++jt){
                int c0 = j0 + jt * 8 + 2 * tg;
                int ksn = c0 >> 4, rem = c0 & 15;
                int mh = rem >> 3, tp = (rem & 7) >> 1;
                #pragma unroll
                for (int rs = 0; rs < 2; ++rs){
                    int rr = i0 + s * 16 + g + rs * 8;
                    uint32_t val = h2(acc[s][jt][rs * 2], acc[s][jt][rs * 2 + 1]);
                    int jb = rr >> 5, jtp = (rr >> 3) & 3, gg = rr & 7;
                    int lidx = (((jb * 8 + ksn) * 32 + gg * 4 + tp) << 2) + (jtp & 1) * 2 + mh;
                    B1u[(jtp >> 1) * 4096 + lidx] = val;
                }
            }
    }

    // ====== G2a: emb0 = S^T X0 ======
    zacc(acc);
    kloop(acc, pAl, pAh, q2l0, q2h0, q2l1, q2h1);
    {
        float* eb = emb + (size_t)b * NN * ND;
        #pragma unroll
        for (int s = 0; s < 2; ++s)
            #pragma unroll
            for (int jt = 0; jt < 8; ++jt){
                int r0 = i0 + s * 16 + g, col = j0 + jt * 8 + 2 * tg;
                *(float2*)(eb + r0 * ND + col)       = make_float2(acc[s][jt][0], acc[s][jt][1]);
                *(float2*)(eb + (r0 + 8) * ND + col) = make_float2(acc[s][jt][2], acc[s][jt][3]);
            }
    }
    __syncthreads();   // T1^T scatter visible; B2 reads done

    // ---- refill B2 with X[:,128:256) ----
    for (int c = tid; c < 2048; c += 256){
        int ln = c & 31, ks = (c >> 5) & 7, jb = (c >> 8) & 3, hf = (c >> 10) & 1;
        int gp = ln >> 2, tp = ln & 3;
        int m0 = ks * 16 + 2 * tp;
        int jA = jb * 32 + hf * 16 + gp + 128, jB = jA + 8;
        (hf ? B2h : B2l)[(jb * 8 + ks) * 32 + ln] = make_uint4(
            h2(xb[m0 * ND + jA], xb[(m0 + 1) * ND + jA]),
            h2(xb[(m0 + 8) * ND + jA], xb[(m0 + 9) * ND + jA]),
            h2(xb[m0 * ND + jB], xb[(m0 + 1) * ND + jB]),
            h2(xb[(m0 + 8) * ND + jB], xb[(m0 + 9) * ND + jB]));
    }

    // ====== G3: nadj^T = S^T T1^T ======
    zacc(acc);
    kloop(acc, pAl, pAh, q1l0, q1h0, q1l1, q1h1);
    {
        float* nb = nadj + (size_t)b * NN * NN;
        #pragma unroll
        for (int s = 0; s < 2; ++s)
            #pragma unroll
            for (int jt = 0; jt < 8; ++jt){
                int col = j0 + jt * 8 + 2 * tg;
                int row = i0 + s * 16 + g;
                nb[col * NN + row]           = acc[s][jt][0];
                nb[(col + 1) * NN + row]     = acc[s][jt][1];
                nb[col * NN + row + 8]       = acc[s][jt][2];
                nb[(col + 1) * NN + row + 8] = acc[s][jt][3];
            }
    }
    __syncthreads();   // B2 refill visible to all

    // ====== G2b: emb1 = S^T X1 ======
    zacc(acc);
    kloop(acc, pAl, pAh, q2l0, q2h0, q2l1, q2h1);
    {
        float* eb = emb + (size_t)b * NN * ND + 128;
        #pragma unroll
        for (int s = 0; s < 2; ++s)
            #pragma unroll
            for (int jt = 0; jt < 8; ++jt){
                int r0 = i0 + s * 16 + g, col = j0 + jt * 8 + 2 * tg;
                *(float2*)(eb + r0 * ND + col)       = make_float2(acc[s][jt][0], acc[s][jt][1]);
                *(float2*)(eb + (r0 + 8) * ND + col) = make_float2(acc[s][jt][2], acc[s][jt][3]);
            }
    }
}

extern "C" void kernel_launch(void* const* d_in, const int* in_sizes, int n_in,
                              void* d_out, int out_size) {
    const float* x    = (const float*)d_in[0];
    const float* adj  = (const float*)d_in[1];
    const int*   head = (const int*)d_in[2];
    const float* lw   = (const float*)d_in[3];
    const float* bias = (const float*)d_in[4];

    float* out  = (float*)d_out;
    float* emb  = out;                            // [B, N, D]
    float* nadj = out + (size_t)NB * NN * ND;     // [B, N, N]

    const int dsmem = 6144 * 16;                  // 98,304 B — 2 CTAs/SM
    cudaFuncSetAttribute(kmain, cudaFuncAttributeMaxDynamicSharedMemorySize, dsmem);
    kmain<<<NB, 256, dsmem>>>(x, adj, head, lw, bias, emb, nadj);
}